// round 16
// baseline (speedup 1.0000x reference)
#include <cuda_runtime.h>
#include <cuda_bf16.h>
#include <math_constants.h>
#include <cstdint>

#define D_MODEL 1024
#define N_HEADS 16
#define HEAD    64
#define BATCH   4
#define SEQ     2048
#define BH      (BATCH * N_HEADS)
#define MTOT    (BATCH * SEQ)   // 8192
#define KDIM    1024

// tcgen05 is arch-SPECIFIC (sm_103a). The harness also emits a plain sm_103
// PTX pass; guard so that pass compiles a correct fallback instead of dying.
#if defined(__CUDA_ARCH__) && defined(__CUDA_ARCH_FEAT_SM103_ALL)
#define HAS_TCGEN05 1
#else
#define HAS_TCGEN05 0
#endif

// K is pre-scaled by log2(e)/8 so softmax uses ex2 directly (p = 2^(s + m*lg2e)).
#define KSCALE 0.1803368801111244f
#define LG2E   1.4426950408889634f

// ---------------- scratch (device globals; no allocation allowed) ----------
// Attention operands, bf16 hi/lo
__device__ unsigned short q_hi[BH * SEQ * HEAD]; // [bh][t][d]
__device__ unsigned short q_lo[BH * SEQ * HEAD];
__device__ unsigned short k_hi[BH * SEQ * HEAD]; // [bh][t][d], pre-scaled log2e/8
__device__ unsigned short k_lo[BH * SEQ * HEAD];
__device__ unsigned short v_hi[BH * HEAD * SEQ]; // [bh][d][t]
__device__ unsigned short v_lo[BH * HEAD * SEQ];

// bf16 split buffers for projections (reused sequentially across stages).
// Attention writes its output (bf16-split) directly into ga_hi/ga_lo.
__device__ __nv_bfloat16 ga_hi[MTOT * KDIM];    // activations [M][K]
__device__ __nv_bfloat16 ga_lo[MTOT * KDIM];
__device__ __nv_bfloat16 gb_hi[2048 * KDIM];    // weights^T [N][K]
__device__ __nv_bfloat16 gb_lo[2048 * KDIM];

// ---------------- PTX helpers ---------------------------------------------
__device__ __forceinline__ uint32_t smem_u32(const void* p) {
    uint32_t a;
    asm("{ .reg .u64 t; cvta.to.shared.u64 t, %1; cvt.u32.u64 %0, t; }"
        : "=r"(a) : "l"(p));
    return a;
}

__device__ __forceinline__ float ex2f(float x) {
    float r;
    asm("ex2.approx.ftz.f32 %0, %1;" : "=f"(r) : "f"(x));
    return r;
}

// Packed fp32 pair -> bf16x2 (round-to-nearest). d = [b_bf16 : a_bf16].
__device__ __forceinline__ uint32_t cvt_bf16x2(float b, float a) {
    uint32_t d;
    asm("cvt.rn.bf16x2.f32 %0, %1, %2;" : "=r"(d) : "f"(b), "f"(a));
    return d;
}

#define SWZ(o) ((o) ^ (((o) >> 3) & 0x70))

#define CP16(dst, src) \
    asm volatile("cp.async.cg.shared.global [%0], [%1], 16;" :: "r"(dst), "l"(src))
#define CP_COMMIT() asm volatile("cp.async.commit_group;" ::: "memory")
#define CP_WAIT1()  asm volatile("cp.async.wait_group 1;" ::: "memory")
#define CP_WAIT0()  asm volatile("cp.async.wait_group 0;" ::: "memory")

#define MBAR_INIT(a, n) \
    asm volatile("mbarrier.init.shared.b64 [%0], %1;" :: "r"(a), "r"(n) : "memory")
#define MBAR_INVAL(a) \
    asm volatile("mbarrier.inval.shared.b64 [%0];" :: "r"(a) : "memory")

#define MBAR_WAIT(a, par) do {                                              \
    uint32_t _m = (a); uint32_t _p = (par); uint32_t _d;                    \
    asm volatile("{ .reg .pred p;"                                          \
        " mbarrier.try_wait.parity.acquire.cta.shared::cta.b64 p, [%1], %2;"\
        " selp.b32 %0, 1, 0, p; }" : "=r"(_d) : "r"(_m), "r"(_p) : "memory");\
    if (!_d) {                                                              \
        asm volatile("{ .reg .pred P1; WL_%=:"                              \
        " mbarrier.try_wait.parity.acquire.cta.shared::cta.b64 P1, [%0], %1, 0x989680;" \
        " @P1 bra.uni WD_%=; bra.uni WL_%=; WD_%=: }"                       \
        :: "r"(_m), "r"(_p) : "memory");                                    \
    } } while (0)

#if HAS_TCGEN05
#define TC_ALLOC(sa, n) \
    asm volatile("tcgen05.alloc.cta_group::1.sync.aligned.shared::cta.b32 [%0], %1;" \
                 :: "r"(sa), "r"(n) : "memory")
#define TC_RELINQ() \
    asm volatile("tcgen05.relinquish_alloc_permit.cta_group::1.sync.aligned;")
#define TC_DEALLOC(t, n) \
    asm volatile("tcgen05.dealloc.cta_group::1.sync.aligned.b32 %0, %1;" :: "r"(t), "r"(n))
#define TC_COMMIT(m) \
    asm volatile("tcgen05.commit.cta_group::1.mbarrier::arrive::one.shared::cluster.b64 [%0];" \
                 :: "r"(m) : "memory")
#define TC_FENCE_AFTER()  asm volatile("tcgen05.fence::after_thread_sync;" ::: "memory")
#define TC_FENCE_BEFORE() asm volatile("tcgen05.fence::before_thread_sync;" ::: "memory")
#define TC_WAIT_LD()      asm volatile("tcgen05.wait::ld.sync.aligned;" ::: "memory")
#define TC_WAIT_ST()      asm volatile("tcgen05.wait::st.sync.aligned;" ::: "memory")
#define FENCE_ASYNC()     asm volatile("fence.proxy.async.shared::cta;" ::: "memory")

#define TC_LD_X32(r, ta) \
    asm volatile("tcgen05.ld.sync.aligned.32x32b.x32.b32 "                  \
        "{%0,%1,%2,%3,%4,%5,%6,%7,%8,%9,%10,%11,%12,%13,%14,%15,"           \
        "%16,%17,%18,%19,%20,%21,%22,%23,%24,%25,%26,%27,%28,%29,%30,%31}, [%32];" \
        : "=r"((r)[0]),"=r"((r)[1]),"=r"((r)[2]),"=r"((r)[3]),              \
          "=r"((r)[4]),"=r"((r)[5]),"=r"((r)[6]),"=r"((r)[7]),              \
          "=r"((r)[8]),"=r"((r)[9]),"=r"((r)[10]),"=r"((r)[11]),            \
          "=r"((r)[12]),"=r"((r)[13]),"=r"((r)[14]),"=r"((r)[15]),          \
          "=r"((r)[16]),"=r"((r)[17]),"=r"((r)[18]),"=r"((r)[19]),          \
          "=r"((r)[20]),"=r"((r)[21]),"=r"((r)[22]),"=r"((r)[23]),          \
          "=r"((r)[24]),"=r"((r)[25]),"=r"((r)[26]),"=r"((r)[27]),          \
          "=r"((r)[28]),"=r"((r)[29]),"=r"((r)[30]),"=r"((r)[31])           \
        : "r"(ta))

#define TC_ST_X16(ta, r) \
    asm volatile("tcgen05.st.sync.aligned.32x32b.x16.b32 [%0], "            \
        "{%1,%2,%3,%4,%5,%6,%7,%8,%9,%10,%11,%12,%13,%14,%15,%16};"         \
        :: "r"(ta),                                                         \
           "r"((r)[0]),"r"((r)[1]),"r"((r)[2]),"r"((r)[3]),                 \
           "r"((r)[4]),"r"((r)[5]),"r"((r)[6]),"r"((r)[7]),                 \
           "r"((r)[8]),"r"((r)[9]),"r"((r)[10]),"r"((r)[11]),               \
           "r"((r)[12]),"r"((r)[13]),"r"((r)[14]),"r"((r)[15])              \
        : "memory")

static constexpr uint64_t DESC_BASE =
    (uint64_t(2) << 61) | (uint64_t(1) << 46) | (uint64_t(64) << 32) | (uint64_t(1) << 16);
#define MK_DESC(addr) (DESC_BASE | ((uint64_t)((addr) >> 4) & 0x3FFF))

// bf16 SS MMA, cta_group::1, fp32 accumulate
__device__ __forceinline__ void mma_bf16_ss(uint32_t d, uint64_t a, uint64_t b,
                                            uint32_t idesc, uint32_t en) {
    asm volatile("{ .reg .pred p; setp.ne.u32 p, %4, 0;"
        " tcgen05.mma.cta_group::1.kind::f16 [%0], %1, %2, %3, {%5,%5,%5,%5}, p; }"
        :: "r"(d), "l"(a), "l"(b), "r"(idesc), "r"(en), "r"(0u) : "memory");
}

// bf16 TS MMA (A in TMEM as bf16x2 columns)
__device__ __forceinline__ void mma_bf16_ts(uint32_t d, uint32_t a, uint64_t b,
                                            uint32_t idesc, uint32_t en) {
    asm volatile("{ .reg .pred p; setp.ne.u32 p, %4, 0;"
        " tcgen05.mma.cta_group::1.kind::f16 [%0], [%1], %2, %3, {%5,%5,%5,%5}, p; }"
        :: "r"(d), "r"(a), "l"(b), "r"(idesc), "r"(en), "r"(0u) : "memory");
}

#define IDESC_128x128 0x8200490u   // M=128, N=128, bf16, f32 acc
#define IDESC_128x64  0x8100490u   // M=128, N=64
#endif  // HAS_TCGEN05

// ---------------- fp32 -> bf16 hi/lo conversion ----------------------------
__device__ __forceinline__ void split2(float v, unsigned short& h, unsigned short& l) {
    __nv_bfloat16 hb = __float2bfloat16_rn(v);
    __nv_bfloat16 lb = __float2bfloat16_rn(v - __bfloat162float(hb));
    h = __bfloat16_as_ushort(hb);
    l = __bfloat16_as_ushort(lb);
}

__global__ void convert_split_kernel(const float* __restrict__ src) {
    const float4* s = (const float4*)src;
    int i = blockIdx.x * blockDim.x + threadIdx.x;   // groups of 4
    float4 v = s[i];
    ushort4 h, l;
    split2(v.x, h.x, l.x);
    split2(v.y, h.y, l.y);
    split2(v.z, h.z, l.z);
    split2(v.w, h.w, l.w);
    ((ushort4*)ga_hi)[i] = h;
    ((ushort4*)ga_lo)[i] = l;
}

// W [K=1024, N] fp32 -> gb_hi/lo [N][K] bf16 (transpose + split)
__global__ void transpose_split_kernel(const float* __restrict__ W, int N) {
    __shared__ float t[32][33];
    const int k0 = blockIdx.y * 32, n0 = blockIdx.x * 32;
    const int x = threadIdx.x, y = threadIdx.y;   // (32, 8)
    #pragma unroll
    for (int j = 0; j < 4; j++) {
        int r = y + j * 8;
        t[r][x] = W[(size_t)(k0 + r) * N + n0 + x];
    }
    __syncthreads();
    #pragma unroll
    for (int j = 0; j < 4; j++) {
        int r = y + j * 8;
        float v = t[x][r];
        unsigned short h, l;
        split2(v, h, l);
        size_t o = (size_t)(n0 + r) * KDIM + k0 + x;
        ((unsigned short*)gb_hi)[o] = h;
        ((unsigned short*)gb_lo)[o] = l;
    }
}

// ---------------- shared projection epilogue -------------------------------
template <int MODE>
__device__ __forceinline__ void epi_store(const uint32_t* r, int pass,
                                          int m0, int n0, int wid, int lid,
                                          const float* __restrict__ bias,
                                          float* __restrict__ C, int N)
{
    const int b = m0 >> 11;
    const int t = (m0 & (SEQ - 1)) + wid * 32 + lid;

    if (MODE == 0) {
        int m = m0 + wid * 32 + lid;
        float* dst = C + (size_t)m * N + n0 + pass * 32;
        const float* bb = bias + n0 + pass * 32;
        #pragma unroll
        for (int c4 = 0; c4 < 8; c4++) {
            float4 o;
            o.x = __uint_as_float(r[c4 * 4 + 0]) + bb[c4 * 4 + 0];
            o.y = __uint_as_float(r[c4 * 4 + 1]) + bb[c4 * 4 + 1];
            o.z = __uint_as_float(r[c4 * 4 + 2]) + bb[c4 * 4 + 2];
            o.w = __uint_as_float(r[c4 * 4 + 3]) + bb[c4 * 4 + 3];
            *(float4*)(dst + c4 * 4) = o;
        }
    } else if (MODE == 1) {
        const int h = n0 >> 7, bh = b * N_HEADS + h;
        if (pass < 2) {   // K: [bh][t][d], pre-scaled log2e/8, bf16 hi/lo
            const int d0 = pass * 32;
            unsigned short hb[32], lb[32];
            #pragma unroll
            for (int c = 0; c < 32; c++) {
                float v = (__uint_as_float(r[c]) + bias[n0 + d0 + c]) * KSCALE;
                split2(v, hb[c], lb[c]);
            }
            unsigned short* dh = k_hi + ((size_t)bh * SEQ + t) * 64 + d0;
            unsigned short* dl = k_lo + ((size_t)bh * SEQ + t) * 64 + d0;
            #pragma unroll
            for (int u = 0; u < 4; u++) {
                ((uint4*)dh)[u] = *(uint4*)&hb[u * 8];
                ((uint4*)dl)[u] = *(uint4*)&lb[u * 8];
            }
        } else {          // V: [bh][d][t], bf16 hi/lo (scattered d rows)
            const int d0 = (pass - 2) * 32;
            #pragma unroll
            for (int c = 0; c < 32; c++) {
                float v = __uint_as_float(r[c]) + bias[n0 + 64 + d0 + c];
                unsigned short h2, l2;
                split2(v, h2, l2);
                size_t o = ((size_t)bh * 64 + d0 + c) * SEQ + t;
                v_hi[o] = h2;
                v_lo[o] = l2;
            }
        }
    } else {              // MODE 2: Q [bh][t][d], bf16 hi/lo (unscaled)
        const int cb = n0 + pass * 32;
        const int h = cb >> 6, d0 = cb & 63, bh = b * N_HEADS + h;
        unsigned short hb[32], lb[32];
        #pragma unroll
        for (int c = 0; c < 32; c++) {
            float v = __uint_as_float(r[c]) + bias[cb + c];
            split2(v, hb[c], lb[c]);
        }
        unsigned short* dh = q_hi + ((size_t)bh * SEQ + t) * 64 + d0;
        unsigned short* dl = q_lo + ((size_t)bh * SEQ + t) * 64 + d0;
        #pragma unroll
        for (int u = 0; u < 4; u++) {
            ((uint4*)dh)[u] = *(uint4*)&hb[u * 8];
            ((uint4*)dl)[u] = *(uint4*)&lb[u * 8];
        }
    }
}

// ---------------- tcgen05 bf16-split projection GEMM -----------------------
#define TILE_B   16384                // 128 rows x 128 bytes
#define STAGE_B  (4 * TILE_B)         // Ahi, Alo, Bhi, Blo
#define TC_SMEM  (1024 + 2 * STAGE_B) // 132096

#if HAS_TCGEN05
__device__ __forceinline__ void tc_load_chunk(
    uint32_t tb, const char* Ah, const char* Al, const char* Bh, const char* Bl,
    int ck, int tid)
{
    #pragma unroll
    for (int j = 0; j < 8; j++) {
        int e = tid + 128 * j;
        int row = e >> 3, c16 = e & 7;
        uint32_t so = SWZ((uint32_t)(row * 128 + c16 * 16));
        size_t go = (size_t)row * 2048 + (size_t)ck * 128 + c16 * 16;
        CP16(tb + 0 * TILE_B + so, Ah + go);
        CP16(tb + 1 * TILE_B + so, Al + go);
        CP16(tb + 2 * TILE_B + so, Bh + go);
        CP16(tb + 3 * TILE_B + so, Bl + go);
    }
    CP_COMMIT();
}
#endif

template <int MODE>
__global__ __launch_bounds__(128)
void tc_gemm(const float* __restrict__ bias, float* __restrict__ C, int N)
{
    const int tid = threadIdx.x, wid = tid >> 5, lid = tid & 31;
    const int m0 = blockIdx.y * 128, n0 = blockIdx.x * 128;

#if HAS_TCGEN05
    extern __shared__ char smem[];
    const uint32_t sb = smem_u32(smem);

    if (tid == 0) { MBAR_INIT(sb + 16, 1); MBAR_INIT(sb + 24, 1); }
    if (wid == 0) { TC_ALLOC(sb, 128); TC_RELINQ(); }
    __syncthreads();
    uint32_t tbase;
    asm volatile("ld.shared.b32 %0, [%1];" : "=r"(tbase) : "r"(sb));

    const char* Ah = (const char*)ga_hi + (size_t)m0 * 2048;
    const char* Al = (const char*)ga_lo + (size_t)m0 * 2048;
    const char* Bh = (const char*)gb_hi + (size_t)n0 * 2048;
    const char* Bl = (const char*)gb_lo + (size_t)n0 * 2048;
    const uint32_t t0s = sb + 1024;

    tc_load_chunk(t0s,           Ah, Al, Bh, Bl, 0, tid);
    tc_load_chunk(t0s + STAGE_B, Ah, Al, Bh, Bl, 1, tid);

    int ph0 = 0, ph1 = 0;
    #pragma unroll 1
    for (int ck = 0; ck < 16; ck++) {
        const int cur = ck & 1;
        if (ck + 1 < 16) { CP_WAIT1(); } else { CP_WAIT0(); }
        __syncthreads();

        if (tid == 0) {
            FENCE_ASYNC();
            uint32_t tb = t0s + cur * STAGE_B;
            uint64_t dah = MK_DESC(tb + 0 * TILE_B);
            uint64_t dal = MK_DESC(tb + 1 * TILE_B);
            uint64_t dbh = MK_DESC(tb + 2 * TILE_B);
            uint64_t dbl = MK_DESC(tb + 3 * TILE_B);
            #pragma unroll
            for (int ks = 0; ks < 4; ks++) {
                uint64_t o = ks * 2;
                mma_bf16_ss(tbase, dah + o, dbh + o, IDESC_128x128,
                            (ck == 0 && ks == 0) ? 0u : 1u);
                mma_bf16_ss(tbase, dah + o, dbl + o, IDESC_128x128, 1u);
                mma_bf16_ss(tbase, dal + o, dbh + o, IDESC_128x128, 1u);
            }
            TC_COMMIT(sb + 16 + cur * 8);
        }

        if (ck + 2 < 16) {
            if (cur == 0) { MBAR_WAIT(sb + 16, ph0); ph0 ^= 1; }
            else          { MBAR_WAIT(sb + 24, ph1); ph1 ^= 1; }
            tc_load_chunk(t0s + cur * STAGE_B, Ah, Al, Bh, Bl, ck + 2, tid);
        }
    }
    MBAR_WAIT(sb + 16, ph0);
    MBAR_WAIT(sb + 24, ph1);
    TC_FENCE_AFTER();

    #pragma unroll 1
    for (int pass = 0; pass < 4; pass++) {
        uint32_t r[32];
        TC_LD_X32(r, tbase + pass * 32);
        TC_WAIT_LD();
        epi_store<MODE>(r, pass, m0, n0, wid, lid, bias, C, N);
    }

    __syncthreads();
    if (tid == 0) { MBAR_INVAL(sb + 16); MBAR_INVAL(sb + 24); }
    __syncthreads();
    if (wid == 0) TC_DEALLOC(tbase, 128);

#else
    // Fallback for the plain-sm_103 PTX pass (never runs on GB300).
    const int row = wid * 32 + lid;
    const __nv_bfloat16* Ah = ga_hi + (size_t)(m0 + row) * KDIM;
    const __nv_bfloat16* Al = ga_lo + (size_t)(m0 + row) * KDIM;
    #pragma unroll 1
    for (int pass = 0; pass < 4; pass++) {
        float acc[32];
        #pragma unroll
        for (int c = 0; c < 32; c++) acc[c] = 0.f;
        #pragma unroll 1
        for (int k = 0; k < KDIM; k++) {
            float a = __bfloat162float(Ah[k]) + __bfloat162float(Al[k]);
            #pragma unroll 1
            for (int c = 0; c < 32; c++) {
                size_t bo = (size_t)(n0 + pass * 32 + c) * KDIM + k;
                float bb = __bfloat162float(gb_hi[bo]) + __bfloat162float(gb_lo[bo]);
                acc[c] = fmaf(a, bb, acc[c]);
            }
        }
        uint32_t r[32];
        #pragma unroll
        for (int c = 0; c < 32; c++) r[c] = __float_as_uint(acc[c]);
        epi_store<MODE>(r, pass, m0, n0, wid, lid, bias, C, N);
    }
#endif
}

// ---------------------------------------------------------------------------
// tcgen05 flash attention, no-max softmax. R16 = the R15 2-CTA/SM skeleton
// with two softmax-local (schedule-preserving) edits:
//   1. mask prefetched into registers BEFORE the S mbar wait (hides LDG
//      latency under the S MMA; ptxas cannot hoist across asm waits itself)
//   2. P hi/lo split via packed cvt.rn.bf16x2 + exact shift-extraction
//      (bf16->fp32 is exact: bits<<16), ~6 instr/pair vs ~10, bit-identical.
// TMEM 256 cols (S0 @0..63, S1 @64..127, O @128..191, PH @192..223,
// PL @224..255); smem 113K (Q 32K | K 2x16K | V 3x16K). 32 tiles of 64.
// ---------------------------------------------------------------------------
#define SM_Q_HI 1024
#define SM_Q_LO (SM_Q_HI + 16384)          // 17408
#define SM_K0   (SM_Q_LO + 16384)          // 33792, 2 bufs x 16384
#define SM_V0   (SM_K0 + 2 * 16384)        // 66560, 3 bufs x 16384
#define AT_SMEM (SM_V0 + 3 * 16384)        // 115712

#define TM_S0   0
#define TM_S1   64
#define TM_O    128
#define TM_PH   192
#define TM_PL   224

#define NTILE   32    // KV tiles of 64

#if HAS_TCGEN05
__device__ __forceinline__ void at_load_kv(uint32_t sb, int bh, int kt,
                                           int kbuf, int vbuf, int tid)
{
    // K tile: 64 t-rows x 64 d = 64 x 128B, hi+lo
    const char* kh = (const char*)k_hi + ((size_t)bh * SEQ + (size_t)kt * 64) * 128;
    const char* kl = (const char*)k_lo + ((size_t)bh * SEQ + (size_t)kt * 64) * 128;
    const uint32_t kb = sb + SM_K0 + kbuf * 16384;
    #pragma unroll
    for (int rep = 0; rep < 2; rep++) {
        int e = tid + rep * 256;           // 0..511
        int row = e >> 3, c = e & 7;
        uint32_t off = SWZ((uint32_t)(row * 128 + c * 16));
        size_t go = (size_t)row * 128 + c * 16;
        CP16(kb + off,        kh + go);
        CP16(kb + 8192 + off, kl + go);
    }
    // V tile: 64 d-rows x 64 t = 64 x 128B (contiguous t-segment per d-row)
    const char* vh = (const char*)v_hi + ((size_t)bh * 64) * (SEQ * 2) + (size_t)kt * 128;
    const char* vl = (const char*)v_lo + ((size_t)bh * 64) * (SEQ * 2) + (size_t)kt * 128;
    const uint32_t vb = sb + SM_V0 + vbuf * 16384;
    #pragma unroll
    for (int rep = 0; rep < 2; rep++) {
        int e = tid + rep * 256;           // 0..511
        int d = e >> 3, c = e & 7;
        uint32_t off = SWZ((uint32_t)(d * 128 + c * 16));
        size_t go = (size_t)d * (SEQ * 2) + c * 16;
        CP16(vb + off,        vh + go);
        CP16(vb + 8192 + off, vl + go);
    }
    CP_COMMIT();
}

__device__ __forceinline__ void at_issue_S(uint32_t sb, uint32_t tb, int sbuf, int kbuf)
{
    FENCE_ASYNC();
    uint64_t dqh = MK_DESC(sb + SM_Q_HI);
    uint64_t dql = MK_DESC(sb + SM_Q_LO);
    uint64_t dkh = MK_DESC(sb + SM_K0 + kbuf * 16384);
    uint64_t dkl = MK_DESC(sb + SM_K0 + kbuf * 16384 + 8192);
    uint32_t dst = tb + (sbuf ? TM_S1 : TM_S0);
    #pragma unroll
    for (int ks = 0; ks < 4; ks++) {
        uint64_t o = ks * 2;
        mma_bf16_ss(dst, dqh + o, dkh + o, IDESC_128x64, ks == 0 ? 0u : 1u);
        mma_bf16_ss(dst, dqh + o, dkl + o, IDESC_128x64, 1u);
        mma_bf16_ss(dst, dql + o, dkh + o, IDESC_128x64, 1u);
    }
    TC_COMMIT(sb + 8 + sbuf * 8);
}

// O += P @ V, TS mode: A = P in TMEM (bf16x2 cols), B = V in smem.
__device__ __forceinline__ void at_issue_O_ts(uint32_t sb, uint32_t tb, int j, int vbuf)
{
    const uint32_t dst = tb + TM_O;
    const uint32_t vb  = sb + SM_V0 + vbuf * 16384;
    #pragma unroll
    for (int ks = 0; ks < 4; ks++) {
        uint64_t o = (uint64_t)ks * 2;
        uint64_t dvh = MK_DESC(vb) + o;
        uint64_t dvl = MK_DESC(vb + 8192) + o;
        uint32_t at = ks * 8;
        mma_bf16_ts(dst, tb + TM_PH + at, dvh, IDESC_128x64,
                    (j == 0 && ks == 0) ? 0u : 1u);
        mma_bf16_ts(dst, tb + TM_PH + at, dvl, IDESC_128x64, 1u);
        mma_bf16_ts(dst, tb + TM_PL + at, dvh, IDESC_128x64, 1u);
    }
    TC_COMMIT(sb + 24);
}
#endif

__global__ __launch_bounds__(256, 2)
void attn_tc(const float* __restrict__ mask)
{
    const int tid = threadIdx.x, wid = tid >> 5, lid = tid & 31;
    const int bh = blockIdx.x, b = bh >> 4, h = bh & 15;
    const int q0 = blockIdx.y * 128;

#if HAS_TCGEN05
    extern __shared__ char smem[];
    const uint32_t sb = smem_u32(smem);

    if (tid == 0) { MBAR_INIT(sb + 8, 1); MBAR_INIT(sb + 16, 1); MBAR_INIT(sb + 24, 1); }
    if (wid == 0) { TC_ALLOC(sb, 256); TC_RELINQ(); }
    __syncthreads();
    uint32_t tb;
    asm volatile("ld.shared.b32 %0, [%1];" : "=r"(tb) : "r"(sb));

    // Q tile load (grouped with KV0)
    {
        const char* qh = (const char*)q_hi + ((size_t)bh * SEQ + q0) * 128;
        const char* ql = (const char*)q_lo + ((size_t)bh * SEQ + q0) * 128;
        #pragma unroll
        for (int rep = 0; rep < 4; rep++) {
            int e = tid + rep * 256;
            int row = e >> 3, c = e & 7;
            uint32_t off = SWZ((uint32_t)(row * 128 + c * 16));
            size_t go = (size_t)row * 128 + c * 16;
            CP16(sb + SM_Q_HI + off, qh + go);
            CP16(sb + SM_Q_LO + off, ql + go);
        }
    }
    at_load_kv(sb, bh, 0, 0, 0, tid);      // group: Q + tile0
    at_load_kv(sb, bh, 1, 1, 1, tid);      // group: tile1
    CP_WAIT1();
    __syncthreads();
    if (tid == 0) at_issue_S(sb, tb, 0, 0);

    int phS0 = 0, phS1 = 0, phO = 0;
    const int rrow = (wid & 3) * 32 + lid;    // local q row (TMEM lane)
    const int ch   = wid >> 2;                // kv-column half (0/1), 32 cols each
    const uint32_t woff = (uint32_t)(wid & 3) << 21;
    float l_acc = 0.f;
    const float* mrow = mask + ((size_t)(b * SEQ + q0 + rrow)) * SEQ;

    #pragma unroll 1
    for (int j = 0; j < NTILE; j++) {
        const int bj = j & 1;

        // ---- mask prefetch for this tile (pure register loads; issued
        //      BEFORE the S wait so LDG latency hides under the S MMA) ----
        const float* mp = mrow + (size_t)j * 64 + ch * 32;
        float4 mk0 = *(const float4*)(mp + 0);
        float4 mk1 = *(const float4*)(mp + 4);
        float4 mk2 = *(const float4*)(mp + 8);
        float4 mk3 = *(const float4*)(mp + 12);
        float4 mk4 = *(const float4*)(mp + 16);
        float4 mk5 = *(const float4*)(mp + 20);
        float4 mk6 = *(const float4*)(mp + 24);
        float4 mk7 = *(const float4*)(mp + 28);

        // wait S_j, read + exp
        if (bj == 0) { MBAR_WAIT(sb + 8,  phS0); phS0 ^= 1; }
        else         { MBAR_WAIT(sb + 16, phS1); phS1 ^= 1; }
        TC_FENCE_AFTER();

        uint32_t r0[32];
        TC_LD_X32(r0, tb + (bj ? TM_S1 : TM_S0) + ch * 32);
        TC_WAIT_LD();

        // softmax: p = 2^(s + m*log2e)
        {
            float4 mv;
            #define SFX(base, MV)                                                 \
                mv = MV;                                                          \
                {                                                                 \
                    float p0 = ex2f(fmaf(mv.x, LG2E, __uint_as_float(r0[base+0])));\
                    float p1 = ex2f(fmaf(mv.y, LG2E, __uint_as_float(r0[base+1])));\
                    float p2 = ex2f(fmaf(mv.z, LG2E, __uint_as_float(r0[base+2])));\
                    float p3 = ex2f(fmaf(mv.w, LG2E, __uint_as_float(r0[base+3])));\
                    l_acc += (p0 + p1) + (p2 + p3);                               \
                    r0[base+0] = __float_as_uint(p0);                             \
                    r0[base+1] = __float_as_uint(p1);                             \
                    r0[base+2] = __float_as_uint(p2);                             \
                    r0[base+3] = __float_as_uint(p3);                             \
                }
            SFX(0,  mk0) SFX(4,  mk1) SFX(8,  mk2) SFX(12, mk3)
            SFX(16, mk4) SFX(20, mk5) SFX(24, mk6) SFX(28, mk7)
            #undef SFX
        }

        // K_{j+1}/V_{j+1} ready? then issue S_{j+1}
        if (j < NTILE - 1) { CP_WAIT0(); }
        __syncthreads();
        if (j < NTILE - 1 && tid == 0) at_issue_S(sb, tb, (j + 1) & 1, (j + 1) & 1);

        // O_{j-1} done -> P TMEM cols free + V buf (j+2)%3 free
        if (j > 0) { MBAR_WAIT(sb + 24, phO); phO ^= 1; TC_FENCE_AFTER(); }

        // prefetch tile j+2 (K buf j&1 read by S_j; V buf (j+2)%3 by O_{j-1})
        if (j + 2 < NTILE) at_load_kv(sb, bh, j + 2, j & 1, (j + 2) % 3, tid);

        // P_j -> TMEM as bf16x2 (hi/lo), cols [ch*16 .. +15]
        // hi via packed cvt; lo via exact shift-extraction (bit-identical to
        // the scalar split: bf16->fp32 is exact).
        {
            uint32_t hw[16], lw[16];
            #pragma unroll
            for (int i = 0; i < 16; i++) {
                float pa = __uint_as_float(r0[i * 2 + 0]);
                float pb = __uint_as_float(r0[i * 2 + 1]);
                uint32_t hv = cvt_bf16x2(pb, pa);        // [pb_hi : pa_hi]
                float fa = __uint_as_float(hv << 16);
                float fb = __uint_as_float(hv & 0xFFFF0000u);
                hw[i] = hv;
                lw[i] = cvt_bf16x2(pb - fb, pa - fa);
            }
            TC_ST_X16(tb + TM_PH + ch * 16 + woff, hw);
            TC_ST_X16(tb + TM_PL + ch * 16 + woff, lw);
            TC_WAIT_ST();
        }
        TC_FENCE_BEFORE();
        __syncthreads();
        if (tid == 0) at_issue_O_ts(sb, tb, j, j % 3);
    }

    // wait final O
    MBAR_WAIT(sb + 24, phO);
    TC_FENCE_AFTER();

    uint32_t o[32];
    TC_LD_X32(o, tb + TM_O + ch * 32);
    TC_WAIT_LD();
    __syncthreads();
    float* l2 = (float*)(smem + SM_K0);    // reuse K buffer for l exchange
    l2[rrow * 2 + ch] = l_acc;
    __syncthreads();
    const float inv = 1.0f / (l2[rrow * 2] + l2[rrow * 2 + 1]);

    // write bf16-split attention output directly into ga (input of out-proj)
    {
        unsigned short hb[32], lb[32];
        #pragma unroll
        for (int c = 0; c < 32; c++)
            split2(__uint_as_float(o[c]) * inv, hb[c], lb[c]);
        size_t base = ((size_t)(b * SEQ + q0 + rrow)) * KDIM + h * 64 + ch * 32;
        unsigned short* dh = (unsigned short*)ga_hi + base;
        unsigned short* dl = (unsigned short*)ga_lo + base;
        #pragma unroll
        for (int u = 0; u < 4; u++) {
            ((uint4*)dh)[u] = *(uint4*)&hb[u * 8];
            ((uint4*)dl)[u] = *(uint4*)&lb[u * 8];
        }
    }

    __syncthreads();
    if (tid == 0) { MBAR_INVAL(sb + 8); MBAR_INVAL(sb + 16); MBAR_INVAL(sb + 24); }
    __syncthreads();
    if (wid == 0) TC_DEALLOC(tb, 256);

#else
    // Fallback for the plain-sm_103 PTX pass (never runs on GB300).
    if (tid < 128) {
        const int q = q0 + tid;
        const unsigned short* qh = q_hi + ((size_t)bh * SEQ + q) * 64;
        const unsigned short* ql = q_lo + ((size_t)bh * SEQ + q) * 64;
        float o[64];
        #pragma unroll
        for (int d = 0; d < 64; d++) o[d] = 0.f;
        float l = 0.f;
        for (int t = 0; t < SEQ; t++) {
            const unsigned short* kh = k_hi + ((size_t)bh * SEQ + t) * 64;
            const unsigned short* kl = k_lo + ((size_t)bh * SEQ + t) * 64;
            float s = 0.f;
            for (int d = 0; d < 64; d++) {
                float qv = __bfloat162float(__ushort_as_bfloat16(qh[d]))
                         + __bfloat162float(__ushort_as_bfloat16(ql[d]));
                float kv = __bfloat162float(__ushort_as_bfloat16(kh[d]))
                         + __bfloat162float(__ushort_as_bfloat16(kl[d]));
                s = fmaf(qv, kv, s);
            }
            float p = exp2f(fmaf(mask[((size_t)(b * SEQ + q)) * SEQ + t], LG2E, s));
            l += p;
            for (int d = 0; d < 64; d++) {
                size_t vo = ((size_t)bh * 64 + d) * SEQ + t;
                float vv = __bfloat162float(__ushort_as_bfloat16(v_hi[vo]))
                         + __bfloat162float(__ushort_as_bfloat16(v_lo[vo]));
                o[d] = fmaf(p, vv, o[d]);
            }
        }
        float inv = 1.0f / l;
        for (int d = 0; d < 64; d++) {
            unsigned short h2, l2v;
            split2(o[d] * inv, h2, l2v);
            size_t base = ((size_t)(b * SEQ + q)) * KDIM + h * 64 + d;
            ((unsigned short*)ga_hi)[base] = h2;
            ((unsigned short*)ga_lo)[base] = l2v;
        }
    }
#endif
}

// ---------------------------------------------------------------------------
extern "C" void kernel_launch(void* const* d_in, const int* in_sizes, int n_in,
                              void* d_out, int out_size)
{
    const float* x_enc = (const float*)d_in[0];
    const float* x_dec = (const float*)d_in[1];
    const float* mask  = (const float*)d_in[2];
    const float* Wq    = (const float*)d_in[3];
    const float* bq    = (const float*)d_in[4];
    const float* Wkv   = (const float*)d_in[5];
    const float* bkv   = (const float*)d_in[6];
    const float* Wo    = (const float*)d_in[7];
    const float* bo    = (const float*)d_in[8];
    float* out = (float*)d_out;

    cudaFuncSetAttribute(tc_gemm<0>, cudaFuncAttributeMaxDynamicSharedMemorySize, TC_SMEM);
    cudaFuncSetAttribute(tc_gemm<1>, cudaFuncAttributeMaxDynamicSharedMemorySize, TC_SMEM);
    cudaFuncSetAttribute(tc_gemm<2>, cudaFuncAttributeMaxDynamicSharedMemorySize, TC_SMEM);
    cudaFuncSetAttribute(attn_tc, cudaFuncAttributeMaxDynamicSharedMemorySize, AT_SMEM);

    const dim3 tb(32, 8);
    const int conv_blocks = (MTOT * KDIM / 4) / 256;   // 8192

    // 1) KV projection -> k_hi/lo ([bh][t][d], scaled), v_hi/lo ([bh][d][t])
    transpose_split_kernel<<<dim3(2048 / 32, KDIM / 32), tb>>>(Wkv, 2048);
    convert_split_kernel<<<conv_blocks, 256>>>(x_enc);
    tc_gemm<1><<<dim3(16, MTOT / 128), 128, TC_SMEM>>>(bkv, nullptr, 2048);

    // 2) Q projection -> q_hi/lo ([bh][t][d])
    transpose_split_kernel<<<dim3(1024 / 32, KDIM / 32), tb>>>(Wq, 1024);
    convert_split_kernel<<<conv_blocks, 256>>>(x_dec);
    tc_gemm<2><<<dim3(8, MTOT / 128), 128, TC_SMEM>>>(bq, nullptr, 1024);

    // 3) tensor-core flash attention (2 CTAs/SM) -> ga_hi/ga_lo
    attn_tc<<<dim3(BH, SEQ / 128), 256, AT_SMEM>>>(mask);

    // 4) Output projection: ga @ Wo + bo -> out
    transpose_split_kernel<<<dim3(1024 / 32, KDIM / 32), tb>>>(Wo, 1024);
    tc_gemm<0><<<dim3(8, MTOT / 128), 128, TC_SMEM>>>(bo, out, 1024);
}

// round 17
// speedup vs baseline: 1.4521x; 1.4521x over previous
#include <cuda_runtime.h>
#include <cuda_bf16.h>
#include <math_constants.h>
#include <cstdint>

#define D_MODEL 1024
#define N_HEADS 16
#define HEAD    64
#define BATCH   4
#define SEQ     2048
#define BH      (BATCH * N_HEADS)
#define MTOT    (BATCH * SEQ)   // 8192
#define KDIM    1024

// tcgen05 is arch-SPECIFIC (sm_103a). The harness also emits a plain sm_103
// PTX pass; guard so that pass compiles a correct fallback instead of dying.
#if defined(__CUDA_ARCH__) && defined(__CUDA_ARCH_FEAT_SM103_ALL)
#define HAS_TCGEN05 1
#else
#define HAS_TCGEN05 0
#endif

// K is pre-scaled by log2(e)/8 so softmax uses ex2 directly (p = 2^(s + m*lg2e)).
#define KSCALE 0.1803368801111244f
#define LG2E   1.4426950408889634f

// ---------------- scratch (device globals; no allocation allowed) ----------
// Attention operands, bf16 hi/lo
__device__ unsigned short q_hi[BH * SEQ * HEAD]; // [bh][t][d]
__device__ unsigned short q_lo[BH * SEQ * HEAD];
__device__ unsigned short k_hi[BH * SEQ * HEAD]; // [bh][t][d], pre-scaled log2e/8
__device__ unsigned short k_lo[BH * SEQ * HEAD];
__device__ unsigned short v_hi[BH * HEAD * SEQ]; // [bh][d][t]
__device__ unsigned short v_lo[BH * HEAD * SEQ];

// bf16 split buffers for projections (reused sequentially across stages).
// Attention writes its output (bf16-split) directly into ga_hi/ga_lo.
__device__ __nv_bfloat16 ga_hi[MTOT * KDIM];    // activations [M][K]
__device__ __nv_bfloat16 ga_lo[MTOT * KDIM];
__device__ __nv_bfloat16 gb_hi[2048 * KDIM];    // weights^T [N][K]
__device__ __nv_bfloat16 gb_lo[2048 * KDIM];

// ---------------- PTX helpers ---------------------------------------------
__device__ __forceinline__ uint32_t smem_u32(const void* p) {
    uint32_t a;
    asm("{ .reg .u64 t; cvta.to.shared.u64 t, %1; cvt.u32.u64 %0, t; }"
        : "=r"(a) : "l"(p));
    return a;
}

__device__ __forceinline__ float ex2f(float x) {
    float r;
    asm("ex2.approx.ftz.f32 %0, %1;" : "=f"(r) : "f"(x));
    return r;
}

// Packed fp32 pair -> bf16x2 (round-to-nearest). d = [b_bf16 : a_bf16].
__device__ __forceinline__ uint32_t cvt_bf16x2(float b, float a) {
    uint32_t d;
    asm("cvt.rn.bf16x2.f32 %0, %1, %2;" : "=r"(d) : "f"(b), "f"(a));
    return d;
}

#define SWZ(o) ((o) ^ (((o) >> 3) & 0x70))

#define CP16(dst, src) \
    asm volatile("cp.async.cg.shared.global [%0], [%1], 16;" :: "r"(dst), "l"(src))
#define CP_COMMIT() asm volatile("cp.async.commit_group;" ::: "memory")
#define CP_WAIT1()  asm volatile("cp.async.wait_group 1;" ::: "memory")
#define CP_WAIT0()  asm volatile("cp.async.wait_group 0;" ::: "memory")

#define MBAR_INIT(a, n) \
    asm volatile("mbarrier.init.shared.b64 [%0], %1;" :: "r"(a), "r"(n) : "memory")
#define MBAR_INVAL(a) \
    asm volatile("mbarrier.inval.shared.b64 [%0];" :: "r"(a) : "memory")

#define MBAR_WAIT(a, par) do {                                              \
    uint32_t _m = (a); uint32_t _p = (par); uint32_t _d;                    \
    asm volatile("{ .reg .pred p;"                                          \
        " mbarrier.try_wait.parity.acquire.cta.shared::cta.b64 p, [%1], %2;"\
        " selp.b32 %0, 1, 0, p; }" : "=r"(_d) : "r"(_m), "r"(_p) : "memory");\
    if (!_d) {                                                              \
        asm volatile("{ .reg .pred P1; WL_%=:"                              \
        " mbarrier.try_wait.parity.acquire.cta.shared::cta.b64 P1, [%0], %1, 0x989680;" \
        " @P1 bra.uni WD_%=; bra.uni WL_%=; WD_%=: }"                       \
        :: "r"(_m), "r"(_p) : "memory");                                    \
    } } while (0)

#if HAS_TCGEN05
#define TC_ALLOC(sa, n) \
    asm volatile("tcgen05.alloc.cta_group::1.sync.aligned.shared::cta.b32 [%0], %1;" \
                 :: "r"(sa), "r"(n) : "memory")
#define TC_RELINQ() \
    asm volatile("tcgen05.relinquish_alloc_permit.cta_group::1.sync.aligned;")
#define TC_DEALLOC(t, n) \
    asm volatile("tcgen05.dealloc.cta_group::1.sync.aligned.b32 %0, %1;" :: "r"(t), "r"(n))
#define TC_COMMIT(m) \
    asm volatile("tcgen05.commit.cta_group::1.mbarrier::arrive::one.shared::cluster.b64 [%0];" \
                 :: "r"(m) : "memory")
#define TC_FENCE_AFTER()  asm volatile("tcgen05.fence::after_thread_sync;" ::: "memory")
#define TC_FENCE_BEFORE() asm volatile("tcgen05.fence::before_thread_sync;" ::: "memory")
#define TC_WAIT_LD()      asm volatile("tcgen05.wait::ld.sync.aligned;" ::: "memory")
#define TC_WAIT_ST()      asm volatile("tcgen05.wait::st.sync.aligned;" ::: "memory")
#define FENCE_ASYNC()     asm volatile("fence.proxy.async.shared::cta;" ::: "memory")

#define TC_LD_X32(r, ta) \
    asm volatile("tcgen05.ld.sync.aligned.32x32b.x32.b32 "                  \
        "{%0,%1,%2,%3,%4,%5,%6,%7,%8,%9,%10,%11,%12,%13,%14,%15,"           \
        "%16,%17,%18,%19,%20,%21,%22,%23,%24,%25,%26,%27,%28,%29,%30,%31}, [%32];" \
        : "=r"((r)[0]),"=r"((r)[1]),"=r"((r)[2]),"=r"((r)[3]),              \
          "=r"((r)[4]),"=r"((r)[5]),"=r"((r)[6]),"=r"((r)[7]),              \
          "=r"((r)[8]),"=r"((r)[9]),"=r"((r)[10]),"=r"((r)[11]),            \
          "=r"((r)[12]),"=r"((r)[13]),"=r"((r)[14]),"=r"((r)[15]),          \
          "=r"((r)[16]),"=r"((r)[17]),"=r"((r)[18]),"=r"((r)[19]),          \
          "=r"((r)[20]),"=r"((r)[21]),"=r"((r)[22]),"=r"((r)[23]),          \
          "=r"((r)[24]),"=r"((r)[25]),"=r"((r)[26]),"=r"((r)[27]),          \
          "=r"((r)[28]),"=r"((r)[29]),"=r"((r)[30]),"=r"((r)[31])           \
        : "r"(ta))

#define TC_ST_X16(ta, r) \
    asm volatile("tcgen05.st.sync.aligned.32x32b.x16.b32 [%0], "            \
        "{%1,%2,%3,%4,%5,%6,%7,%8,%9,%10,%11,%12,%13,%14,%15,%16};"         \
        :: "r"(ta),                                                         \
           "r"((r)[0]),"r"((r)[1]),"r"((r)[2]),"r"((r)[3]),                 \
           "r"((r)[4]),"r"((r)[5]),"r"((r)[6]),"r"((r)[7]),                 \
           "r"((r)[8]),"r"((r)[9]),"r"((r)[10]),"r"((r)[11]),               \
           "r"((r)[12]),"r"((r)[13]),"r"((r)[14]),"r"((r)[15])              \
        : "memory")

static constexpr uint64_t DESC_BASE =
    (uint64_t(2) << 61) | (uint64_t(1) << 46) | (uint64_t(64) << 32) | (uint64_t(1) << 16);
#define MK_DESC(addr) (DESC_BASE | ((uint64_t)((addr) >> 4) & 0x3FFF))

// bf16 SS MMA, cta_group::1, fp32 accumulate
__device__ __forceinline__ void mma_bf16_ss(uint32_t d, uint64_t a, uint64_t b,
                                            uint32_t idesc, uint32_t en) {
    asm volatile("{ .reg .pred p; setp.ne.u32 p, %4, 0;"
        " tcgen05.mma.cta_group::1.kind::f16 [%0], %1, %2, %3, {%5,%5,%5,%5}, p; }"
        :: "r"(d), "l"(a), "l"(b), "r"(idesc), "r"(en), "r"(0u) : "memory");
}

// bf16 TS MMA (A in TMEM as bf16x2 columns)
__device__ __forceinline__ void mma_bf16_ts(uint32_t d, uint32_t a, uint64_t b,
                                            uint32_t idesc, uint32_t en) {
    asm volatile("{ .reg .pred p; setp.ne.u32 p, %4, 0;"
        " tcgen05.mma.cta_group::1.kind::f16 [%0], [%1], %2, %3, {%5,%5,%5,%5}, p; }"
        :: "r"(d), "r"(a), "l"(b), "r"(idesc), "r"(en), "r"(0u) : "memory");
}

#define IDESC_128x128 0x8200490u   // M=128, N=128, bf16, f32 acc
#define IDESC_128x64  0x8100490u   // M=128, N=64
#endif  // HAS_TCGEN05

// ---------------- fp32 -> bf16 hi/lo conversion ----------------------------
__device__ __forceinline__ void split2(float v, unsigned short& h, unsigned short& l) {
    __nv_bfloat16 hb = __float2bfloat16_rn(v);
    __nv_bfloat16 lb = __float2bfloat16_rn(v - __bfloat162float(hb));
    h = __bfloat16_as_ushort(hb);
    l = __bfloat16_as_ushort(lb);
}

__global__ void convert_split_kernel(const float* __restrict__ src) {
    const float4* s = (const float4*)src;
    int i = blockIdx.x * blockDim.x + threadIdx.x;   // groups of 4
    float4 v = s[i];
    ushort4 h, l;
    split2(v.x, h.x, l.x);
    split2(v.y, h.y, l.y);
    split2(v.z, h.z, l.z);
    split2(v.w, h.w, l.w);
    ((ushort4*)ga_hi)[i] = h;
    ((ushort4*)ga_lo)[i] = l;
}

// W [K=1024, N] fp32 -> gb_hi/lo [N][K] bf16 (transpose + split)
__global__ void transpose_split_kernel(const float* __restrict__ W, int N) {
    __shared__ float t[32][33];
    const int k0 = blockIdx.y * 32, n0 = blockIdx.x * 32;
    const int x = threadIdx.x, y = threadIdx.y;   // (32, 8)
    #pragma unroll
    for (int j = 0; j < 4; j++) {
        int r = y + j * 8;
        t[r][x] = W[(size_t)(k0 + r) * N + n0 + x];
    }
    __syncthreads();
    #pragma unroll
    for (int j = 0; j < 4; j++) {
        int r = y + j * 8;
        float v = t[x][r];
        unsigned short h, l;
        split2(v, h, l);
        size_t o = (size_t)(n0 + r) * KDIM + k0 + x;
        ((unsigned short*)gb_hi)[o] = h;
        ((unsigned short*)gb_lo)[o] = l;
    }
}

// ---------------- shared projection epilogue -------------------------------
template <int MODE>
__device__ __forceinline__ void epi_store(const uint32_t* r, int pass,
                                          int m0, int n0, int wid, int lid,
                                          const float* __restrict__ bias,
                                          float* __restrict__ C, int N)
{
    const int b = m0 >> 11;
    const int t = (m0 & (SEQ - 1)) + wid * 32 + lid;

    if (MODE == 0) {
        int m = m0 + wid * 32 + lid;
        float* dst = C + (size_t)m * N + n0 + pass * 32;
        const float* bb = bias + n0 + pass * 32;
        #pragma unroll
        for (int c4 = 0; c4 < 8; c4++) {
            float4 o;
            o.x = __uint_as_float(r[c4 * 4 + 0]) + bb[c4 * 4 + 0];
            o.y = __uint_as_float(r[c4 * 4 + 1]) + bb[c4 * 4 + 1];
            o.z = __uint_as_float(r[c4 * 4 + 2]) + bb[c4 * 4 + 2];
            o.w = __uint_as_float(r[c4 * 4 + 3]) + bb[c4 * 4 + 3];
            *(float4*)(dst + c4 * 4) = o;
        }
    } else if (MODE == 1) {
        const int h = n0 >> 7, bh = b * N_HEADS + h;
        if (pass < 2) {   // K: [bh][t][d], pre-scaled log2e/8, bf16 hi/lo
            const int d0 = pass * 32;
            unsigned short hb[32], lb[32];
            #pragma unroll
            for (int c = 0; c < 32; c++) {
                float v = (__uint_as_float(r[c]) + bias[n0 + d0 + c]) * KSCALE;
                split2(v, hb[c], lb[c]);
            }
            unsigned short* dh = k_hi + ((size_t)bh * SEQ + t) * 64 + d0;
            unsigned short* dl = k_lo + ((size_t)bh * SEQ + t) * 64 + d0;
            #pragma unroll
            for (int u = 0; u < 4; u++) {
                ((uint4*)dh)[u] = *(uint4*)&hb[u * 8];
                ((uint4*)dl)[u] = *(uint4*)&lb[u * 8];
            }
        } else {          // V: [bh][d][t], bf16 hi/lo (scattered d rows)
            const int d0 = (pass - 2) * 32;
            #pragma unroll
            for (int c = 0; c < 32; c++) {
                float v = __uint_as_float(r[c]) + bias[n0 + 64 + d0 + c];
                unsigned short h2, l2;
                split2(v, h2, l2);
                size_t o = ((size_t)bh * 64 + d0 + c) * SEQ + t;
                v_hi[o] = h2;
                v_lo[o] = l2;
            }
        }
    } else {              // MODE 2: Q [bh][t][d], bf16 hi/lo (unscaled)
        const int cb = n0 + pass * 32;
        const int h = cb >> 6, d0 = cb & 63, bh = b * N_HEADS + h;
        unsigned short hb[32], lb[32];
        #pragma unroll
        for (int c = 0; c < 32; c++) {
            float v = __uint_as_float(r[c]) + bias[cb + c];
            split2(v, hb[c], lb[c]);
        }
        unsigned short* dh = q_hi + ((size_t)bh * SEQ + t) * 64 + d0;
        unsigned short* dl = q_lo + ((size_t)bh * SEQ + t) * 64 + d0;
        #pragma unroll
        for (int u = 0; u < 4; u++) {
            ((uint4*)dh)[u] = *(uint4*)&hb[u * 8];
            ((uint4*)dl)[u] = *(uint4*)&lb[u * 8];
        }
    }
}

// ---------------- tcgen05 bf16-split projection GEMM -----------------------
#define TILE_B   16384                // 128 rows x 128 bytes
#define STAGE_B  (4 * TILE_B)         // Ahi, Alo, Bhi, Blo
#define TC_SMEM  (1024 + 2 * STAGE_B) // 132096

#if HAS_TCGEN05
__device__ __forceinline__ void tc_load_chunk(
    uint32_t tb, const char* Ah, const char* Al, const char* Bh, const char* Bl,
    int ck, int tid)
{
    #pragma unroll
    for (int j = 0; j < 8; j++) {
        int e = tid + 128 * j;
        int row = e >> 3, c16 = e & 7;
        uint32_t so = SWZ((uint32_t)(row * 128 + c16 * 16));
        size_t go = (size_t)row * 2048 + (size_t)ck * 128 + c16 * 16;
        CP16(tb + 0 * TILE_B + so, Ah + go);
        CP16(tb + 1 * TILE_B + so, Al + go);
        CP16(tb + 2 * TILE_B + so, Bh + go);
        CP16(tb + 3 * TILE_B + so, Bl + go);
    }
    CP_COMMIT();
}
#endif

template <int MODE>
__global__ __launch_bounds__(128)
void tc_gemm(const float* __restrict__ bias, float* __restrict__ C, int N)
{
    const int tid = threadIdx.x, wid = tid >> 5, lid = tid & 31;
    const int m0 = blockIdx.y * 128, n0 = blockIdx.x * 128;

#if HAS_TCGEN05
    extern __shared__ char smem[];
    const uint32_t sb = smem_u32(smem);

    if (tid == 0) { MBAR_INIT(sb + 16, 1); MBAR_INIT(sb + 24, 1); }
    if (wid == 0) { TC_ALLOC(sb, 128); TC_RELINQ(); }
    __syncthreads();
    uint32_t tbase;
    asm volatile("ld.shared.b32 %0, [%1];" : "=r"(tbase) : "r"(sb));

    const char* Ah = (const char*)ga_hi + (size_t)m0 * 2048;
    const char* Al = (const char*)ga_lo + (size_t)m0 * 2048;
    const char* Bh = (const char*)gb_hi + (size_t)n0 * 2048;
    const char* Bl = (const char*)gb_lo + (size_t)n0 * 2048;
    const uint32_t t0s = sb + 1024;

    tc_load_chunk(t0s,           Ah, Al, Bh, Bl, 0, tid);
    tc_load_chunk(t0s + STAGE_B, Ah, Al, Bh, Bl, 1, tid);

    int ph0 = 0, ph1 = 0;
    #pragma unroll 1
    for (int ck = 0; ck < 16; ck++) {
        const int cur = ck & 1;
        if (ck + 1 < 16) { CP_WAIT1(); } else { CP_WAIT0(); }
        __syncthreads();

        if (tid == 0) {
            FENCE_ASYNC();
            uint32_t tb = t0s + cur * STAGE_B;
            uint64_t dah = MK_DESC(tb + 0 * TILE_B);
            uint64_t dal = MK_DESC(tb + 1 * TILE_B);
            uint64_t dbh = MK_DESC(tb + 2 * TILE_B);
            uint64_t dbl = MK_DESC(tb + 3 * TILE_B);
            #pragma unroll
            for (int ks = 0; ks < 4; ks++) {
                uint64_t o = ks * 2;
                mma_bf16_ss(tbase, dah + o, dbh + o, IDESC_128x128,
                            (ck == 0 && ks == 0) ? 0u : 1u);
                mma_bf16_ss(tbase, dah + o, dbl + o, IDESC_128x128, 1u);
                mma_bf16_ss(tbase, dal + o, dbh + o, IDESC_128x128, 1u);
            }
            TC_COMMIT(sb + 16 + cur * 8);
        }

        if (ck + 2 < 16) {
            if (cur == 0) { MBAR_WAIT(sb + 16, ph0); ph0 ^= 1; }
            else          { MBAR_WAIT(sb + 24, ph1); ph1 ^= 1; }
            tc_load_chunk(t0s + cur * STAGE_B, Ah, Al, Bh, Bl, ck + 2, tid);
        }
    }
    MBAR_WAIT(sb + 16, ph0);
    MBAR_WAIT(sb + 24, ph1);
    TC_FENCE_AFTER();

    #pragma unroll 1
    for (int pass = 0; pass < 4; pass++) {
        uint32_t r[32];
        TC_LD_X32(r, tbase + pass * 32);
        TC_WAIT_LD();
        epi_store<MODE>(r, pass, m0, n0, wid, lid, bias, C, N);
    }

    __syncthreads();
    if (tid == 0) { MBAR_INVAL(sb + 16); MBAR_INVAL(sb + 24); }
    __syncthreads();
    if (wid == 0) TC_DEALLOC(tbase, 128);

#else
    // Fallback for the plain-sm_103 PTX pass (never runs on GB300).
    const int row = wid * 32 + lid;
    const __nv_bfloat16* Ah = ga_hi + (size_t)(m0 + row) * KDIM;
    const __nv_bfloat16* Al = ga_lo + (size_t)(m0 + row) * KDIM;
    #pragma unroll 1
    for (int pass = 0; pass < 4; pass++) {
        float acc[32];
        #pragma unroll
        for (int c = 0; c < 32; c++) acc[c] = 0.f;
        #pragma unroll 1
        for (int k = 0; k < KDIM; k++) {
            float a = __bfloat162float(Ah[k]) + __bfloat162float(Al[k]);
            #pragma unroll 1
            for (int c = 0; c < 32; c++) {
                size_t bo = (size_t)(n0 + pass * 32 + c) * KDIM + k;
                float bb = __bfloat162float(gb_hi[bo]) + __bfloat162float(gb_lo[bo]);
                acc[c] = fmaf(a, bb, acc[c]);
            }
        }
        uint32_t r[32];
        #pragma unroll
        for (int c = 0; c < 32; c++) r[c] = __float_as_uint(acc[c]);
        epi_store<MODE>(r, pass, m0, n0, wid, lid, bias, C, N);
    }
#endif
}

// ---------------------------------------------------------------------------
// tcgen05 flash attention, no-max softmax. R17 = the R15 2-CTA/SM skeleton
// byte-for-byte (best: 762.6us) + ONE register-neutral edit: P hi/lo split
// via packed cvt.rn.bf16x2 + exact shift-extraction (bf16->fp32 via bits<<16
// is exact), ~6 instr/pair vs ~10, bit-identical numerics. The R16 mask
// prefetch is REVERTED (it widened live ranges across the S-wait and caused
// spills under the 2-CTA register cap -> 1085us regression).
// TMEM 256 cols (S0 @0..63, S1 @64..127, O @128..191, PH @192..223,
// PL @224..255); smem 113K (Q 32K | K 2x16K | V 3x16K). 32 tiles of 64.
// ---------------------------------------------------------------------------
#define SM_Q_HI 1024
#define SM_Q_LO (SM_Q_HI + 16384)          // 17408
#define SM_K0   (SM_Q_LO + 16384)          // 33792, 2 bufs x 16384
#define SM_V0   (SM_K0 + 2 * 16384)        // 66560, 3 bufs x 16384
#define AT_SMEM (SM_V0 + 3 * 16384)        // 115712

#define TM_S0   0
#define TM_S1   64
#define TM_O    128
#define TM_PH   192
#define TM_PL   224

#define NTILE   32    // KV tiles of 64

#if HAS_TCGEN05
__device__ __forceinline__ void at_load_kv(uint32_t sb, int bh, int kt,
                                           int kbuf, int vbuf, int tid)
{
    // K tile: 64 t-rows x 64 d = 64 x 128B, hi+lo
    const char* kh = (const char*)k_hi + ((size_t)bh * SEQ + (size_t)kt * 64) * 128;
    const char* kl = (const char*)k_lo + ((size_t)bh * SEQ + (size_t)kt * 64) * 128;
    const uint32_t kb = sb + SM_K0 + kbuf * 16384;
    #pragma unroll
    for (int rep = 0; rep < 2; rep++) {
        int e = tid + rep * 256;           // 0..511
        int row = e >> 3, c = e & 7;
        uint32_t off = SWZ((uint32_t)(row * 128 + c * 16));
        size_t go = (size_t)row * 128 + c * 16;
        CP16(kb + off,        kh + go);
        CP16(kb + 8192 + off, kl + go);
    }
    // V tile: 64 d-rows x 64 t = 64 x 128B (contiguous t-segment per d-row)
    const char* vh = (const char*)v_hi + ((size_t)bh * 64) * (SEQ * 2) + (size_t)kt * 128;
    const char* vl = (const char*)v_lo + ((size_t)bh * 64) * (SEQ * 2) + (size_t)kt * 128;
    const uint32_t vb = sb + SM_V0 + vbuf * 16384;
    #pragma unroll
    for (int rep = 0; rep < 2; rep++) {
        int e = tid + rep * 256;           // 0..511
        int d = e >> 3, c = e & 7;
        uint32_t off = SWZ((uint32_t)(d * 128 + c * 16));
        size_t go = (size_t)d * (SEQ * 2) + c * 16;
        CP16(vb + off,        vh + go);
        CP16(vb + 8192 + off, vl + go);
    }
    CP_COMMIT();
}

__device__ __forceinline__ void at_issue_S(uint32_t sb, uint32_t tb, int sbuf, int kbuf)
{
    FENCE_ASYNC();
    uint64_t dqh = MK_DESC(sb + SM_Q_HI);
    uint64_t dql = MK_DESC(sb + SM_Q_LO);
    uint64_t dkh = MK_DESC(sb + SM_K0 + kbuf * 16384);
    uint64_t dkl = MK_DESC(sb + SM_K0 + kbuf * 16384 + 8192);
    uint32_t dst = tb + (sbuf ? TM_S1 : TM_S0);
    #pragma unroll
    for (int ks = 0; ks < 4; ks++) {
        uint64_t o = ks * 2;
        mma_bf16_ss(dst, dqh + o, dkh + o, IDESC_128x64, ks == 0 ? 0u : 1u);
        mma_bf16_ss(dst, dqh + o, dkl + o, IDESC_128x64, 1u);
        mma_bf16_ss(dst, dql + o, dkh + o, IDESC_128x64, 1u);
    }
    TC_COMMIT(sb + 8 + sbuf * 8);
}

// O += P @ V, TS mode: A = P in TMEM (bf16x2 cols), B = V in smem.
__device__ __forceinline__ void at_issue_O_ts(uint32_t sb, uint32_t tb, int j, int vbuf)
{
    const uint32_t dst = tb + TM_O;
    const uint32_t vb  = sb + SM_V0 + vbuf * 16384;
    #pragma unroll
    for (int ks = 0; ks < 4; ks++) {
        uint64_t o = (uint64_t)ks * 2;
        uint64_t dvh = MK_DESC(vb) + o;
        uint64_t dvl = MK_DESC(vb + 8192) + o;
        uint32_t at = ks * 8;
        mma_bf16_ts(dst, tb + TM_PH + at, dvh, IDESC_128x64,
                    (j == 0 && ks == 0) ? 0u : 1u);
        mma_bf16_ts(dst, tb + TM_PH + at, dvl, IDESC_128x64, 1u);
        mma_bf16_ts(dst, tb + TM_PL + at, dvh, IDESC_128x64, 1u);
    }
    TC_COMMIT(sb + 24);
}
#endif

__global__ __launch_bounds__(256, 2)
void attn_tc(const float* __restrict__ mask)
{
    const int tid = threadIdx.x, wid = tid >> 5, lid = tid & 31;
    const int bh = blockIdx.x, b = bh >> 4, h = bh & 15;
    const int q0 = blockIdx.y * 128;

#if HAS_TCGEN05
    extern __shared__ char smem[];
    const uint32_t sb = smem_u32(smem);

    if (tid == 0) { MBAR_INIT(sb + 8, 1); MBAR_INIT(sb + 16, 1); MBAR_INIT(sb + 24, 1); }
    if (wid == 0) { TC_ALLOC(sb, 256); TC_RELINQ(); }
    __syncthreads();
    uint32_t tb;
    asm volatile("ld.shared.b32 %0, [%1];" : "=r"(tb) : "r"(sb));

    // Q tile load (grouped with KV0)
    {
        const char* qh = (const char*)q_hi + ((size_t)bh * SEQ + q0) * 128;
        const char* ql = (const char*)q_lo + ((size_t)bh * SEQ + q0) * 128;
        #pragma unroll
        for (int rep = 0; rep < 4; rep++) {
            int e = tid + rep * 256;
            int row = e >> 3, c = e & 7;
            uint32_t off = SWZ((uint32_t)(row * 128 + c * 16));
            size_t go = (size_t)row * 128 + c * 16;
            CP16(sb + SM_Q_HI + off, qh + go);
            CP16(sb + SM_Q_LO + off, ql + go);
        }
    }
    at_load_kv(sb, bh, 0, 0, 0, tid);      // group: Q + tile0
    at_load_kv(sb, bh, 1, 1, 1, tid);      // group: tile1
    CP_WAIT1();
    __syncthreads();
    if (tid == 0) at_issue_S(sb, tb, 0, 0);

    int phS0 = 0, phS1 = 0, phO = 0;
    const int rrow = (wid & 3) * 32 + lid;    // local q row (TMEM lane)
    const int ch   = wid >> 2;                // kv-column half (0/1), 32 cols each
    const uint32_t woff = (uint32_t)(wid & 3) << 21;
    float l_acc = 0.f;

    #pragma unroll 1
    for (int j = 0; j < NTILE; j++) {
        const int bj = j & 1;

        // wait S_j, read + exp
        if (bj == 0) { MBAR_WAIT(sb + 8,  phS0); phS0 ^= 1; }
        else         { MBAR_WAIT(sb + 16, phS1); phS1 ^= 1; }
        TC_FENCE_AFTER();

        uint32_t r0[32];
        TC_LD_X32(r0, tb + (bj ? TM_S1 : TM_S0) + ch * 32);
        TC_WAIT_LD();

        // softmax: p = 2^(s + m*log2e)
        const float* mp = mask + ((size_t)(b * SEQ + q0 + rrow)) * SEQ
                        + (size_t)j * 64 + ch * 32;
        #pragma unroll
        for (int c4 = 0; c4 < 8; c4++) {
            float4 mv = *(const float4*)(mp + c4 * 4);
            float p0 = ex2f(fmaf(mv.x, LG2E, __uint_as_float(r0[c4 * 4 + 0])));
            float p1 = ex2f(fmaf(mv.y, LG2E, __uint_as_float(r0[c4 * 4 + 1])));
            float p2 = ex2f(fmaf(mv.z, LG2E, __uint_as_float(r0[c4 * 4 + 2])));
            float p3 = ex2f(fmaf(mv.w, LG2E, __uint_as_float(r0[c4 * 4 + 3])));
            l_acc += (p0 + p1) + (p2 + p3);
            r0[c4 * 4 + 0] = __float_as_uint(p0);
            r0[c4 * 4 + 1] = __float_as_uint(p1);
            r0[c4 * 4 + 2] = __float_as_uint(p2);
            r0[c4 * 4 + 3] = __float_as_uint(p3);
        }

        // K_{j+1}/V_{j+1} ready? then issue S_{j+1}
        if (j < NTILE - 1) { CP_WAIT0(); }
        __syncthreads();
        if (j < NTILE - 1 && tid == 0) at_issue_S(sb, tb, (j + 1) & 1, (j + 1) & 1);

        // O_{j-1} done -> P TMEM cols free + V buf (j+2)%3 free
        if (j > 0) { MBAR_WAIT(sb + 24, phO); phO ^= 1; TC_FENCE_AFTER(); }

        // prefetch tile j+2 (K buf j&1 read by S_j; V buf (j+2)%3 by O_{j-1})
        if (j + 2 < NTILE) at_load_kv(sb, bh, j + 2, j & 1, (j + 2) % 3, tid);

        // P_j -> TMEM as bf16x2 (hi/lo), cols [ch*16 .. +15]
        // hi via packed cvt; lo via exact shift-extraction (bf16->fp32 via
        // bits<<16 is exact) -> bit-identical to the scalar split, fewer ops.
        {
            uint32_t hw[16], lw[16];
            #pragma unroll
            for (int i = 0; i < 16; i++) {
                float pa = __uint_as_float(r0[i * 2 + 0]);
                float pb = __uint_as_float(r0[i * 2 + 1]);
                uint32_t hv = cvt_bf16x2(pb, pa);        // [pb_hi : pa_hi]
                float fa = __uint_as_float(hv << 16);
                float fb = __uint_as_float(hv & 0xFFFF0000u);
                hw[i] = hv;
                lw[i] = cvt_bf16x2(pb - fb, pa - fa);
            }
            TC_ST_X16(tb + TM_PH + ch * 16 + woff, hw);
            TC_ST_X16(tb + TM_PL + ch * 16 + woff, lw);
            TC_WAIT_ST();
        }
        TC_FENCE_BEFORE();
        __syncthreads();
        if (tid == 0) at_issue_O_ts(sb, tb, j, j % 3);
    }

    // wait final O
    MBAR_WAIT(sb + 24, phO);
    TC_FENCE_AFTER();

    uint32_t o[32];
    TC_LD_X32(o, tb + TM_O + ch * 32);
    TC_WAIT_LD();
    __syncthreads();
    float* l2 = (float*)(smem + SM_K0);    // reuse K buffer for l exchange
    l2[rrow * 2 + ch] = l_acc;
    __syncthreads();
    const float inv = 1.0f / (l2[rrow * 2] + l2[rrow * 2 + 1]);

    // write bf16-split attention output directly into ga (input of out-proj)
    {
        unsigned short hb[32], lb[32];
        #pragma unroll
        for (int c = 0; c < 32; c++)
            split2(__uint_as_float(o[c]) * inv, hb[c], lb[c]);
        size_t base = ((size_t)(b * SEQ + q0 + rrow)) * KDIM + h * 64 + ch * 32;
        unsigned short* dh = (unsigned short*)ga_hi + base;
        unsigned short* dl = (unsigned short*)ga_lo + base;
        #pragma unroll
        for (int u = 0; u < 4; u++) {
            ((uint4*)dh)[u] = *(uint4*)&hb[u * 8];
            ((uint4*)dl)[u] = *(uint4*)&lb[u * 8];
        }
    }

    __syncthreads();
    if (tid == 0) { MBAR_INVAL(sb + 8); MBAR_INVAL(sb + 16); MBAR_INVAL(sb + 24); }
    __syncthreads();
    if (wid == 0) TC_DEALLOC(tb, 256);

#else
    // Fallback for the plain-sm_103 PTX pass (never runs on GB300).
    if (tid < 128) {
        const int q = q0 + tid;
        const unsigned short* qh = q_hi + ((size_t)bh * SEQ + q) * 64;
        const unsigned short* ql = q_lo + ((size_t)bh * SEQ + q) * 64;
        float o[64];
        #pragma unroll
        for (int d = 0; d < 64; d++) o[d] = 0.f;
        float l = 0.f;
        for (int t = 0; t < SEQ; t++) {
            const unsigned short* kh = k_hi + ((size_t)bh * SEQ + t) * 64;
            const unsigned short* kl = k_lo + ((size_t)bh * SEQ + t) * 64;
            float s = 0.f;
            for (int d = 0; d < 64; d++) {
                float qv = __bfloat162float(__ushort_as_bfloat16(qh[d]))
                         + __bfloat162float(__ushort_as_bfloat16(ql[d]));
                float kv = __bfloat162float(__ushort_as_bfloat16(kh[d]))
                         + __bfloat162float(__ushort_as_bfloat16(kl[d]));
                s = fmaf(qv, kv, s);
            }
            float p = exp2f(fmaf(mask[((size_t)(b * SEQ + q)) * SEQ + t], LG2E, s));
            l += p;
            for (int d = 0; d < 64; d++) {
                size_t vo = ((size_t)bh * 64 + d) * SEQ + t;
                float vv = __bfloat162float(__ushort_as_bfloat16(v_hi[vo]))
                         + __bfloat162float(__ushort_as_bfloat16(v_lo[vo]));
                o[d] = fmaf(p, vv, o[d]);
            }
        }
        float inv = 1.0f / l;
        for (int d = 0; d < 64; d++) {
            unsigned short h2, l2v;
            split2(o[d] * inv, h2, l2v);
            size_t base = ((size_t)(b * SEQ + q)) * KDIM + h * 64 + d;
            ((unsigned short*)ga_hi)[base] = h2;
            ((unsigned short*)ga_lo)[base] = l2v;
        }
    }
#endif
}

// ---------------------------------------------------------------------------
extern "C" void kernel_launch(void* const* d_in, const int* in_sizes, int n_in,
                              void* d_out, int out_size)
{
    const float* x_enc = (const float*)d_in[0];
    const float* x_dec = (const float*)d_in[1];
    const float* mask  = (const float*)d_in[2];
    const float* Wq    = (const float*)d_in[3];
    const float* bq    = (const float*)d_in[4];
    const float* Wkv   = (const float*)d_in[5];
    const float* bkv   = (const float*)d_in[6];
    const float* Wo    = (const float*)d_in[7];
    const float* bo    = (const float*)d_in[8];
    float* out = (float*)d_out;

    cudaFuncSetAttribute(tc_gemm<0>, cudaFuncAttributeMaxDynamicSharedMemorySize, TC_SMEM);
    cudaFuncSetAttribute(tc_gemm<1>, cudaFuncAttributeMaxDynamicSharedMemorySize, TC_SMEM);
    cudaFuncSetAttribute(tc_gemm<2>, cudaFuncAttributeMaxDynamicSharedMemorySize, TC_SMEM);
    cudaFuncSetAttribute(attn_tc, cudaFuncAttributeMaxDynamicSharedMemorySize, AT_SMEM);

    const dim3 tb(32, 8);
    const int conv_blocks = (MTOT * KDIM / 4) / 256;   // 8192

    // 1) KV projection -> k_hi/lo ([bh][t][d], scaled), v_hi/lo ([bh][d][t])
    transpose_split_kernel<<<dim3(2048 / 32, KDIM / 32), tb>>>(Wkv, 2048);
    convert_split_kernel<<<conv_blocks, 256>>>(x_enc);
    tc_gemm<1><<<dim3(16, MTOT / 128), 128, TC_SMEM>>>(bkv, nullptr, 2048);

    // 2) Q projection -> q_hi/lo ([bh][t][d])
    transpose_split_kernel<<<dim3(1024 / 32, KDIM / 32), tb>>>(Wq, 1024);
    convert_split_kernel<<<conv_blocks, 256>>>(x_dec);
    tc_gemm<2><<<dim3(8, MTOT / 128), 128, TC_SMEM>>>(bq, nullptr, 1024);

    // 3) tensor-core flash attention (2 CTAs/SM) -> ga_hi/ga_lo
    attn_tc<<<dim3(BH, SEQ / 128), 256, AT_SMEM>>>(mask);

    // 4) Output projection: ga @ Wo + bo -> out
    transpose_split_kernel<<<dim3(1024 / 32, KDIM / 32), tb>>>(Wo, 1024);
    tc_gemm<0><<<dim3(8, MTOT / 128), 128, TC_SMEM>>>(bo, out, 1024);
}